// round 1
// baseline (speedup 1.0000x reference)
#include <cuda_runtime.h>
#include <cuda_bf16.h>

// Problem constants
#define S_DIM   64
#define N_DIM   384
#define C_IN    64
#define C_H     32
#define C_OUT   128
#define KTOT    1024          // C_H*C_H
#define AB_COLS (N_DIM * C_H) // 12288
#define LN_EPS  1e-5f

// Scratch (allocation-free rule: __device__ globals)
__device__ float g_A[S_DIM * AB_COLS];     // A[s][n*32+c], masked projection a
__device__ float g_B[S_DIM * AB_COLS];     // B[s][n*32+d], masked projection b
__device__ float g_WoT[KTOT * C_OUT];      // WoT[k][o] = Wo[o][k]

// ---------------------------------------------------------------------------
// Kernel 1: LayerNorm + dual projection + mask  ->  g_A, g_B
// One warp per (s,n) row. Block = 256 threads = 8 rows.
// ---------------------------------------------------------------------------
__global__ __launch_bounds__(256) void prep_kernel(
    const float* __restrict__ m, const int* __restrict__ mask,
    const float* __restrict__ gamma, const float* __restrict__ beta,
    const float* __restrict__ Wa, const float* __restrict__ Wb)
{
    __shared__ float sWaT[C_IN * C_H];   // [k][c] transposed, conflict-free reads
    __shared__ float sWbT[C_IN * C_H];
    __shared__ float sMn[8][C_IN];

    for (int i = threadIdx.x; i < C_H * C_IN; i += 256) {
        int c = i >> 6, k = i & 63;      // Wa[c][k]
        sWaT[k * C_H + c] = Wa[i];
        sWbT[k * C_H + c] = Wb[i];
    }
    __syncthreads();

    int warp = threadIdx.x >> 5;
    int lane = threadIdx.x & 31;
    int row  = blockIdx.x * 8 + warp;          // row = s*384 + n
    if (row >= S_DIM * N_DIM) return;

    const float* mp = m + (size_t)row * C_IN;
    float v0 = mp[lane], v1 = mp[lane + 32];

    float sum = v0 + v1;
    #pragma unroll
    for (int o = 16; o; o >>= 1) sum += __shfl_xor_sync(0xffffffffu, sum, o);
    float mu = sum * (1.f / 64.f);
    float d0 = v0 - mu, d1 = v1 - mu;
    float sq = d0 * d0 + d1 * d1;
    #pragma unroll
    for (int o = 16; o; o >>= 1) sq += __shfl_xor_sync(0xffffffffu, sq, o);
    float inv = rsqrtf(sq * (1.f / 64.f) + LN_EPS);

    float mn0 = d0 * inv * gamma[lane]      + beta[lane];
    float mn1 = d1 * inv * gamma[lane + 32] + beta[lane + 32];
    sMn[warp][lane]      = mn0;
    sMn[warp][lane + 32] = mn1;
    __syncwarp();

    float mf = (float)mask[row];
    float aa = 0.f, bb = 0.f;
    #pragma unroll
    for (int k = 0; k < C_IN; k++) {
        float x = sMn[warp][k];
        aa += x * sWaT[k * C_H + lane];
        bb += x * sWbT[k * C_H + lane];
    }
    int s = row / N_DIM, n = row % N_DIM;
    g_A[s * AB_COLS + n * C_H + lane] = aa * mf;
    g_B[s * AB_COLS + n * C_H + lane] = bb * mf;
}

// ---------------------------------------------------------------------------
// Kernel 2: transpose Wo[o][k] -> WoT[k][o]
// ---------------------------------------------------------------------------
__global__ void transpose_wo(const float* __restrict__ Wo)
{
    int idx = blockIdx.x * 256 + threadIdx.x;      // 131072 elements
    if (idx < C_OUT * KTOT) {
        int o = idx >> 10, k = idx & 1023;
        g_WoT[k * C_OUT + o] = Wo[idx];
    }
}

// ---------------------------------------------------------------------------
// Kernel 3: main fused kernel. One CTA = 4x4 (i,j) tile.
//   Stage 1: load A-tile/B-tile (64 x 128 each) to smem
//   Stage 2: GEMM1  Z(128x128) = A^T B  (K=64), 8x8 register micro-tiles
//   Stage 3: GEMM2  out(16x128) = Zflat(16x1024) @ WoT, 4-way k-split
//   Stage 4: smem reduction, /denom, +bo, store
// ---------------------------------------------------------------------------
#define TI 4
#define TJ 4
#define PADZ 132
#define SMEM_FLOATS (128 * PADZ + 32)   // Zs + invd scratch

__global__ __launch_bounds__(256) void main_kernel(
    const int* __restrict__ mask,
    const float* __restrict__ bo,
    float* __restrict__ out)
{
    extern __shared__ float sm[];
    float* As    = sm;                 // [64][128] (stage 1/2 only)
    float* Bs    = sm + 8192;          // [64][128]
    float* Zs    = sm;                 // [128][PADZ] (stage 2/3, aliases As/Bs)
    float* red   = sm;                 // [4][16][128] partials (stage 4, aliases Zs)
    float* sInvd = sm + 128 * PADZ;    // [16]

    const int t  = threadIdx.x;
    const int ti = blockIdx.x, tj = blockIdx.y;

    // --- pairwise mask denominators (16 pairs), fully unrolled for MLP ---
    if (t < 16) {
        int ii = t >> 2, jj = t & 3;
        const int* mi = mask + ti * TI + ii;
        const int* mj = mask + tj * TJ + jj;
        int dsum = 0;
        #pragma unroll
        for (int s = 0; s < S_DIM; s++)
            dsum += mi[s * N_DIM] * mj[s * N_DIM];
        float d = (float)dsum;
        sInvd[t] = 1.f / fmaxf(d, 1.f);
    }

    // --- stage 1: load tiles ---
    {
        const float4* A4 = (const float4*)g_A;   // row stride 3072 float4
        const float4* B4 = (const float4*)g_B;
        float4* As4 = (float4*)As;
        float4* Bs4 = (float4*)Bs;
        #pragma unroll
        for (int idx = t; idx < 64 * 32; idx += 256) {
            int k = idx >> 5, q = idx & 31;
            As4[k * 32 + q] = A4[k * 3072 + ti * 32 + q];
            Bs4[k * 32 + q] = B4[k * 3072 + tj * 32 + q];
        }
    }
    __syncthreads();

    // --- stage 2: GEMM1 Z = A^T B, thread (tx,ty) owns 8x8 ---
    const int tx = t & 15, ty = t >> 4;
    float acc[8][8];
    #pragma unroll
    for (int iy = 0; iy < 8; iy++)
        #pragma unroll
        for (int ix = 0; ix < 8; ix++) acc[iy][ix] = 0.f;

    #pragma unroll 4
    for (int k = 0; k < 64; k++) {
        float av[8], bv[8];
        *(float4*)&av[0] = *(const float4*)&As[k * 128 + ty * 8];
        *(float4*)&av[4] = *(const float4*)&As[k * 128 + ty * 8 + 4];
        *(float4*)&bv[0] = *(const float4*)&Bs[k * 128 + tx * 8];
        *(float4*)&bv[4] = *(const float4*)&Bs[k * 128 + tx * 8 + 4];
        #pragma unroll
        for (int iy = 0; iy < 8; iy++)
            #pragma unroll
            for (int ix = 0; ix < 8; ix++)
                acc[iy][ix] += av[iy] * bv[ix];
    }
    __syncthreads();   // As/Bs reads done; Zs may now overwrite

    #pragma unroll
    for (int iy = 0; iy < 8; iy++) {
        int r = ty * 8 + iy;
        *(float4*)&Zs[r * PADZ + tx * 8]     = make_float4(acc[iy][0], acc[iy][1], acc[iy][2], acc[iy][3]);
        *(float4*)&Zs[r * PADZ + tx * 8 + 4] = make_float4(acc[iy][4], acc[iy][5], acc[iy][6], acc[iy][7]);
    }
    __syncthreads();

    // --- stage 3: GEMM2, 4-way k-split: thread = (ks, pg=ii, oi) ---
    const int ks = t >> 6;          // k-slice 0..3 (k in [ks*256, ks*256+256))
    const int t6 = t & 63;
    const int pg = t6 >> 4;         // ii = 0..3
    const int oi = t6 & 15;         // o block: o in [oi*8, oi*8+8)

    float oacc[4][8];               // [jj][u]
    #pragma unroll
    for (int jj = 0; jj < 4; jj++)
        #pragma unroll
        for (int u = 0; u < 8; u++) oacc[jj][u] = 0.f;

    {
        const float4* wp = (const float4*)g_WoT + (size_t)(ks * 256) * 32 + oi * 2;
        const int kc0 = ks * 8;
        #pragma unroll 1
        for (int kc = 0; kc < 8; kc++) {
            const float* zbase = &Zs[(pg * 32 + kc0 + kc) * PADZ];
            #pragma unroll 4
            for (int kd = 0; kd < 32; kd++) {
                float4 w0 = wp[0];
                float4 w1 = wp[1];
                wp += 32;
                float z0 = zbase[kd];
                float z1 = zbase[32 + kd];
                float z2 = zbase[64 + kd];
                float z3 = zbase[96 + kd];
                float wv[8] = {w0.x, w0.y, w0.z, w0.w, w1.x, w1.y, w1.z, w1.w};
                #pragma unroll
                for (int u = 0; u < 8; u++) {
                    oacc[0][u] += z0 * wv[u];
                    oacc[1][u] += z1 * wv[u];
                    oacc[2][u] += z2 * wv[u];
                    oacc[3][u] += z3 * wv[u];
                }
            }
        }
    }
    __syncthreads();   // Zs reads done; red may overwrite

    // --- stage 4: cross-slice reduction + epilogue ---
    #pragma unroll
    for (int jj = 0; jj < 4; jj++) {
        int p = pg * 4 + jj;
        float* rp = &red[(ks * 16 + p) * 128 + oi * 8];
        *(float4*)&rp[0] = make_float4(oacc[jj][0], oacc[jj][1], oacc[jj][2], oacc[jj][3]);
        *(float4*)&rp[4] = make_float4(oacc[jj][4], oacc[jj][5], oacc[jj][6], oacc[jj][7]);
    }
    __syncthreads();

    {
        int p  = t >> 4;            // pair 0..15
        int ob = (t & 15) * 8;      // o base
        int ii = p >> 2, jj = p & 3;
        float invd = sInvd[p];
        int gi = ti * TI + ii, gj = tj * TJ + jj;
        float* op = out + ((size_t)gi * N_DIM + gj) * C_OUT + ob;
        float res[8];
        #pragma unroll
        for (int u = 0; u < 8; u++) {
            float v = red[(0 * 16 + p) * 128 + ob + u]
                    + red[(1 * 16 + p) * 128 + ob + u]
                    + red[(2 * 16 + p) * 128 + ob + u]
                    + red[(3 * 16 + p) * 128 + ob + u];
            res[u] = v * invd + bo[ob + u];
        }
        *(float4*)&op[0] = make_float4(res[0], res[1], res[2], res[3]);
        *(float4*)&op[4] = make_float4(res[4], res[5], res[6], res[7]);
    }
}

// ---------------------------------------------------------------------------
extern "C" void kernel_launch(void* const* d_in, const int* in_sizes, int n_in,
                              void* d_out, int out_size)
{
    const float* m     = (const float*)d_in[0];
    const int*   mask  = (const int*)  d_in[1];
    const float* gamma = (const float*)d_in[2];
    const float* beta  = (const float*)d_in[3];
    const float* Wa    = (const float*)d_in[4];
    const float* Wb    = (const float*)d_in[5];
    const float* Wo    = (const float*)d_in[6];
    const float* bo    = (const float*)d_in[7];
    float* out = (float*)d_out;

    static_assert(SMEM_FLOATS * 4 < 70 * 1024, "smem budget");
    cudaFuncSetAttribute(main_kernel, cudaFuncAttributeMaxDynamicSharedMemorySize,
                         SMEM_FLOATS * (int)sizeof(float));

    prep_kernel<<<(S_DIM * N_DIM) / 8, 256>>>(m, mask, gamma, beta, Wa, Wb);
    transpose_wo<<<(C_OUT * KTOT + 255) / 256, 256>>>(Wo);

    dim3 grid(N_DIM / TI, N_DIM / TJ);
    main_kernel<<<grid, 256, SMEM_FLOATS * (int)sizeof(float)>>>(mask, bo, out);
}